// round 5
// baseline (speedup 1.0000x reference)
#include <cuda_runtime.h>

// ---------------------------------------------------------------------------
// EdgeNetwork: per-node factorization + 2 edges/thread + f32x2 packed math.
//   pre_k : xs[n] = x[n]@W1a + b1 + vp[batch[n]]@W1c ; xb[n] = x[n]@W1b
//   edge_k: h = xs[s]+xb[d]; 3x(LN+tanh) H=8; channels packed (2j,2j+1) as
//           f32x2; two independent edges interleaved for ILP.
// ---------------------------------------------------------------------------

#define NODE_CAP 131072
typedef unsigned long long u64;

__device__ __align__(16) float g_xs[NODE_CAP * 8];
__device__ __align__(16) float g_xb[NODE_CAP * 8];

__device__ __forceinline__ int detect_is64(const int* __restrict__ ei) {
    int nz = 0;
#pragma unroll
    for (int i = 1; i < 16; i += 2) nz |= ei[i];
    return nz == 0;
}

// ---- f32x2 helpers ----------------------------------------------------------
__device__ __forceinline__ u64 pack2(float lo, float hi) {
    u64 r; asm("mov.b64 %0,{%1,%2};" : "=l"(r) : "f"(lo), "f"(hi)); return r;
}
__device__ __forceinline__ void unpack2(u64 v, float& lo, float& hi) {
    asm("mov.b64 {%0,%1},%2;" : "=f"(lo), "=f"(hi) : "l"(v));
}
__device__ __forceinline__ u64 fma2(u64 a, u64 b, u64 c) {
    u64 d; asm("fma.rn.f32x2 %0,%1,%2,%3;" : "=l"(d) : "l"(a), "l"(b), "l"(c)); return d;
}
__device__ __forceinline__ u64 add2(u64 a, u64 b) {
    u64 d; asm("add.rn.f32x2 %0,%1,%2;" : "=l"(d) : "l"(a), "l"(b)); return d;
}
__device__ __forceinline__ u64 mul2(u64 a, u64 b) {
    u64 d; asm("mul.rn.f32x2 %0,%1,%2;" : "=l"(d) : "l"(a), "l"(b)); return d;
}

// ---------------------------------------------------------------------------
// Per-node precompute
// ---------------------------------------------------------------------------
__global__ void __launch_bounds__(256) pre_k(
    const float* __restrict__ x, const int* __restrict__ batch_raw,
    const float* __restrict__ vp, const float* __restrict__ W1,
    const float* __restrict__ b1, const int* __restrict__ ei, int N, int G)
{
    __shared__ float sW1[48 * 8];
    __shared__ float svp[64 * 16];
    __shared__ float sb1[8];
    __shared__ int sflag;
    int t = threadIdx.x;
    if (t == 0) sflag = detect_is64(ei);
    for (int i = t; i < 384; i += blockDim.x) sW1[i] = W1[i];
    int gv = G * 16; if (gv > 1024) gv = 1024;
    for (int i = t; i < gv; i += blockDim.x) svp[i] = vp[i];
    if (t < 8) sb1[t] = b1[t];
    __syncthreads();

    int n = blockIdx.x * blockDim.x + t;
    if (n >= N) return;

    int g = sflag ? batch_raw[2 * n] : batch_raw[n];

    float xi[16];
    const float* xr = x + (size_t)n * 16;
#pragma unroll
    for (int k = 0; k < 16; k += 4) {
        float4 v = *(const float4*)(xr + k);
        xi[k] = v.x; xi[k + 1] = v.y; xi[k + 2] = v.z; xi[k + 3] = v.w;
    }
    const float* vg = svp + g * 16;

    float xs[8], xb[8];
#pragma unroll
    for (int j = 0; j < 8; j++) {
        float a = sb1[j];
        float b = 0.0f;
#pragma unroll
        for (int k = 0; k < 16; k++) {
            a = fmaf(xi[k], sW1[k * 8 + j], a);
            a = fmaf(vg[k], sW1[(32 + k) * 8 + j], a);
            b = fmaf(xi[k], sW1[(16 + k) * 8 + j], b);
        }
        xs[j] = a; xb[j] = b;
    }
    float4* o1 = (float4*)(g_xs + (size_t)n * 8);
    o1[0] = make_float4(xs[0], xs[1], xs[2], xs[3]);
    o1[1] = make_float4(xs[4], xs[5], xs[6], xs[7]);
    float4* o2 = (float4*)(g_xb + (size_t)n * 8);
    o2[0] = make_float4(xb[0], xb[1], xb[2], xb[3]);
    o2[1] = make_float4(xb[4], xb[5], xb[6], xb[7]);
}

// ---------------------------------------------------------------------------
// Packed LN + tanh: hp[4] = channels (0,1),(2,3),(4,5),(6,7) of one edge.
// tanh via 1 - 2/(e^{2z}+1); the two reciprocals of a pair share one MUFU.RCP
// through rp = 1/(eap*ebp). Outputs 8 scalars.
// ---------------------------------------------------------------------------
__device__ __forceinline__ void ln_tanh_p(
    const u64 hp[4], const u64* __restrict__ gp, const u64* __restrict__ bep,
    float t[8])
{
    u64 s2  = add2(add2(hp[0], hp[1]), add2(hp[2], hp[3]));
    u64 ss2 = fma2(hp[0], hp[0], fma2(hp[1], hp[1],
              fma2(hp[2], hp[2], mul2(hp[3], hp[3]))));
    float sx, sy, qx, qy;
    unpack2(s2, sx, sy); unpack2(ss2, qx, qy);
    float mu  = (sx + sy) * 0.125f;
    float ms  = (qx + qy) * 0.125f;
    float var = fmaf(-mu, mu, ms);
    float r   = rsqrtf(var + 1e-5f);
    u64 mun = pack2(-mu, -mu);
    u64 rd  = pack2(r, r);
    const float K = 2.885390081777927f;  // 2*log2(e)
#pragma unroll
    for (int p = 0; p < 4; p++) {
        u64 Ap = mul2(rd, gp[p]);
        u64 zp = fma2(add2(hp[p], mun), Ap, bep[p]);
        float za, zb;
        unpack2(zp, za, zb);
        float ea, eb, rp;
        asm("ex2.approx.f32 %0, %1;" : "=f"(ea) : "f"(za * K));
        asm("ex2.approx.f32 %0, %1;" : "=f"(eb) : "f"(zb * K));
        float eap = ea + 1.0f, ebp = eb + 1.0f;
        asm("rcp.approx.f32 %0, %1;" : "=f"(rp) : "f"(eap * ebp));
        t[2 * p]     = fmaf(-2.0f * ebp, rp, 1.0f);   // 1 - 2/eap
        t[2 * p + 1] = fmaf(-2.0f * eap, rp, 1.0f);   // 1 - 2/ebp
    }
}

// 8->8 GEMM: wp = u64 view of row-major W (pairs (2p,2p+1) per row k).
__device__ __forceinline__ void gemm8p(
    const float t[8], const u64* __restrict__ wp, const u64* __restrict__ bp,
    u64 acc[4])
{
    u64 td[8];
#pragma unroll
    for (int k = 0; k < 8; k++) td[k] = pack2(t[k], t[k]);
#pragma unroll
    for (int p = 0; p < 4; p++) {
        u64 a = fma2(td[0], wp[p], bp[p]);
#pragma unroll
        for (int k = 1; k < 8; k++) a = fma2(td[k], wp[k * 4 + p], a);
        acc[p] = a;
    }
}

__device__ __forceinline__ float edge_final(
    const float t[8], const u64* __restrict__ w4p, float b4s)
{
    u64 o2 = fma2(pack2(t[0], t[1]), w4p[0],
             fma2(pack2(t[2], t[3]), w4p[1],
             fma2(pack2(t[4], t[5]), w4p[2],
             mul2(pack2(t[6], t[7]), w4p[3]))));
    float ox, oy; unpack2(o2, ox, oy);
    return b4s + ox + oy;
}

__global__ void __launch_bounds__(64) edge_k(
    const int* __restrict__ ei, int E,
    const float* __restrict__ g1, const float* __restrict__ be1,
    const float* __restrict__ W2, const float* __restrict__ b2,
    const float* __restrict__ g2, const float* __restrict__ be2,
    const float* __restrict__ W3, const float* __restrict__ b3,
    const float* __restrict__ g3, const float* __restrict__ be3,
    const float* __restrict__ W4, const float* __restrict__ b4,
    float* __restrict__ out)
{
    __shared__ u64 sW2p[32], sW3p[32], sW4p[4];
    __shared__ u64 sg1p[4], sbe1p[4], sb2p[4], sg2p[4], sbe2p[4];
    __shared__ u64 sb3p[4], sg3p[4], sbe3p[4];
    __shared__ float sb4;
    __shared__ int sflag;

    int t = threadIdx.x;
    if (t == 0) { sflag = detect_is64(ei); sb4 = b4[0]; }
    if (t < 32) {
        sW2p[t] = ((const u64*)W2)[t];
        sW3p[t] = ((const u64*)W3)[t];
    }
    if (t < 4) {
        sW4p[t]  = ((const u64*)W4)[t];
        sg1p[t]  = ((const u64*)g1)[t];
        sbe1p[t] = ((const u64*)be1)[t];
        sb2p[t]  = ((const u64*)b2)[t];
        sg2p[t]  = ((const u64*)g2)[t];
        sbe2p[t] = ((const u64*)be2)[t];
        sb3p[t]  = ((const u64*)b3)[t];
        sg3p[t]  = ((const u64*)g3)[t];
        sbe3p[t] = ((const u64*)be3)[t];
    }
    __syncthreads();

    int is64 = sflag;
    int tid = blockIdx.x * blockDim.x + t;
    int nthreads = gridDim.x * blockDim.x;

    for (int e0 = tid * 2; e0 < E; e0 += nthreads * 2) {
        if (e0 + 1 < E) {
            int s0, s1, d0, d1;
            if (is64) {
                int4 sw = *(const int4*)(ei + 2 * (size_t)e0);
                int4 dw = *(const int4*)(ei + 2 * ((size_t)E + e0));
                s0 = sw.x; s1 = sw.z; d0 = dw.x; d1 = dw.z;
            } else {
                int2 sw = *(const int2*)(ei + e0);
                int2 dw = *(const int2*)(ei + (size_t)E + e0);
                s0 = sw.x; s1 = sw.y; d0 = dw.x; d1 = dw.y;
            }

            const ulonglong2* apA = (const ulonglong2*)(g_xs + (size_t)s0 * 8);
            const ulonglong2* bpA = (const ulonglong2*)(g_xb + (size_t)d0 * 8);
            const ulonglong2* apB = (const ulonglong2*)(g_xs + (size_t)s1 * 8);
            const ulonglong2* bpB = (const ulonglong2*)(g_xb + (size_t)d1 * 8);
            ulonglong2 A0 = apA[0], A1 = apA[1], C0 = bpA[0], C1 = bpA[1];
            ulonglong2 B0 = apB[0], B1 = apB[1], D0 = bpB[0], D1 = bpB[1];

            u64 hA[4] = { add2(A0.x, C0.x), add2(A0.y, C0.y),
                          add2(A1.x, C1.x), add2(A1.y, C1.y) };
            u64 hB[4] = { add2(B0.x, D0.x), add2(B0.y, D0.y),
                          add2(B1.x, D1.x), add2(B1.y, D1.y) };

            float tA[8], tB[8];
            ln_tanh_p(hA, sg1p, sbe1p, tA);   ln_tanh_p(hB, sg1p, sbe1p, tB);
            u64 h2A[4], h2B[4];
            gemm8p(tA, sW2p, sb2p, h2A);      gemm8p(tB, sW2p, sb2p, h2B);
            ln_tanh_p(h2A, sg2p, sbe2p, tA);  ln_tanh_p(h2B, sg2p, sbe2p, tB);
            u64 h3A[4], h3B[4];
            gemm8p(tA, sW3p, sb3p, h3A);      gemm8p(tB, sW3p, sb3p, h3B);
            ln_tanh_p(h3A, sg3p, sbe3p, tA);  ln_tanh_p(h3B, sg3p, sbe3p, tB);

            float oA = edge_final(tA, sW4p, sb4);
            float oB = edge_final(tB, sW4p, sb4);
            *(float2*)(out + e0) = make_float2(oA, oB);
        } else {
            int s, d;
            if (is64) { s = ei[2 * (size_t)e0]; d = ei[2 * ((size_t)E + e0)]; }
            else      { s = ei[e0];             d = ei[(size_t)E + e0]; }
            const ulonglong2* ap = (const ulonglong2*)(g_xs + (size_t)s * 8);
            const ulonglong2* bp = (const ulonglong2*)(g_xb + (size_t)d * 8);
            ulonglong2 A0 = ap[0], A1 = ap[1], C0 = bp[0], C1 = bp[1];
            u64 h[4] = { add2(A0.x, C0.x), add2(A0.y, C0.y),
                         add2(A1.x, C1.x), add2(A1.y, C1.y) };
            float tv[8];
            ln_tanh_p(h, sg1p, sbe1p, tv);
            u64 h2[4]; gemm8p(tv, sW2p, sb2p, h2);
            ln_tanh_p(h2, sg2p, sbe2p, tv);
            u64 h3[4]; gemm8p(tv, sW3p, sb3p, h3);
            ln_tanh_p(h3, sg3p, sbe3p, tv);
            out[e0] = edge_final(tv, sW4p, sb4);
        }
    }
}

// ---------------------------------------------------------------------------
extern "C" void kernel_launch(void* const* d_in, const int* in_sizes, int n_in,
                              void* d_out, int out_size)
{
    const float* x     = (const float*)d_in[0];
    const int*   ei    = (const int*)d_in[1];
    const float* vp    = (const float*)d_in[2];
    const int*   batch = (const int*)d_in[3];
    const float* W1  = (const float*)d_in[4];
    const float* b1  = (const float*)d_in[5];
    const float* g1  = (const float*)d_in[6];
    const float* be1 = (const float*)d_in[7];
    const float* W2  = (const float*)d_in[8];
    const float* b2  = (const float*)d_in[9];
    const float* g2  = (const float*)d_in[10];
    const float* be2 = (const float*)d_in[11];
    const float* W3  = (const float*)d_in[12];
    const float* b3  = (const float*)d_in[13];
    const float* g3  = (const float*)d_in[14];
    const float* be3 = (const float*)d_in[15];
    const float* W4  = (const float*)d_in[16];
    const float* b4  = (const float*)d_in[17];

    int N = in_sizes[0] / 16;
    int E = in_sizes[1] / 2;
    int G = in_sizes[2] / 16;

    int pb = (N + 255) / 256;
    pre_k<<<pb, 256>>>(x, batch, vp, W1, b1, ei, N, G);

    // 2 edges/thread; block=64 for fine occupancy quantization vs regs.
    long long need = ((long long)E / 2 + 63) / 64;
    int eb = need < 4736 ? (int)need : 4736;
    edge_k<<<eb, 64>>>(ei, E, g1, be1, W2, b2, g2, be2, W3, b3, g3, be3,
                       W4, b4, (float*)d_out);
}

// round 6
// speedup vs baseline: 1.1363x; 1.1363x over previous
#include <cuda_runtime.h>

// ---------------------------------------------------------------------------
// EdgeNetwork: per-node factorization + 2 edges/thread (scalar math).
//   pre_k : xs[n] = x[n]@W1a + b1 + vp[batch[n]]@W1c ; xb[n] = x[n]@W1b
//   edge_k: h = xs[s]+xb[d]; 3x(LN+tanh) H=8 in regs, K-folded tanh,
//           next-iteration index prefetch, persistent 1-wave grid.
// ---------------------------------------------------------------------------

#define NODE_CAP 131072
#define KLOG2E 2.8853900817779268f   // 2*log2(e)

__device__ __align__(16) float g_xs[NODE_CAP * 8];
__device__ __align__(16) float g_xb[NODE_CAP * 8];

__device__ __forceinline__ int detect_is64(const int* __restrict__ ei) {
    int nz = 0;
#pragma unroll
    for (int i = 1; i < 16; i += 2) nz |= ei[i];
    return nz == 0;
}

// ---------------------------------------------------------------------------
// Per-node precompute
// ---------------------------------------------------------------------------
__global__ void __launch_bounds__(256) pre_k(
    const float* __restrict__ x, const int* __restrict__ batch_raw,
    const float* __restrict__ vp, const float* __restrict__ W1,
    const float* __restrict__ b1, const int* __restrict__ ei, int N, int G)
{
    __shared__ float sW1[48 * 8];
    __shared__ float svp[64 * 16];
    __shared__ float sb1[8];
    __shared__ int sflag;
    int t = threadIdx.x;
    if (t == 0) sflag = detect_is64(ei);
    for (int i = t; i < 384; i += blockDim.x) sW1[i] = W1[i];
    int gv = G * 16; if (gv > 1024) gv = 1024;
    for (int i = t; i < gv; i += blockDim.x) svp[i] = vp[i];
    if (t < 8) sb1[t] = b1[t];
    __syncthreads();

    int n = blockIdx.x * blockDim.x + t;
    if (n >= N) return;

    int g = sflag ? batch_raw[2 * n] : batch_raw[n];

    float xi[16];
    const float* xr = x + (size_t)n * 16;
#pragma unroll
    for (int k = 0; k < 16; k += 4) {
        float4 v = *(const float4*)(xr + k);
        xi[k] = v.x; xi[k + 1] = v.y; xi[k + 2] = v.z; xi[k + 3] = v.w;
    }
    const float* vg = svp + g * 16;

    float xs[8], xb[8];
#pragma unroll
    for (int j = 0; j < 8; j++) {
        float a = sb1[j];
        float b = 0.0f;
#pragma unroll
        for (int k = 0; k < 16; k++) {
            a = fmaf(xi[k], sW1[k * 8 + j], a);
            a = fmaf(vg[k], sW1[(32 + k) * 8 + j], a);
            b = fmaf(xi[k], sW1[(16 + k) * 8 + j], b);
        }
        xs[j] = a; xb[j] = b;
    }
    float4* o1 = (float4*)(g_xs + (size_t)n * 8);
    o1[0] = make_float4(xs[0], xs[1], xs[2], xs[3]);
    o1[1] = make_float4(xs[4], xs[5], xs[6], xs[7]);
    float4* o2 = (float4*)(g_xb + (size_t)n * 8);
    o2[0] = make_float4(xb[0], xb[1], xb[2], xb[3]);
    o2[1] = make_float4(xb[4], xb[5], xb[6], xb[7]);
}

// ---------------------------------------------------------------------------
// LN + tanh, K-folded: ex2 input = (h-mu)*(K*r)*g + K*be, per channel:
//   w = P*g[j]; c = fma(-mu,w,kbe[j]); z = fma(h,w,c);
//   t = 1 - 2*rcp(ex2(z)+1)
// 5 fma-pipe + 2 MUFU per channel. In-place on h[8].
// ---------------------------------------------------------------------------
__device__ __forceinline__ void ln_tanh(float h[8], const float* __restrict__ g,
                                        const float* __restrict__ kbe) {
    float s = ((h[0] + h[1]) + (h[2] + h[3])) + ((h[4] + h[5]) + (h[6] + h[7]));
    float ss = 0.0f;
#pragma unroll
    for (int j = 0; j < 8; j++) ss = fmaf(h[j], h[j], ss);
    float mu = s * 0.125f;
    float var = fmaf(-mu, mu, ss * 0.125f);
    float r = rsqrtf(var + 1e-5f);
    float P = r * KLOG2E;
#pragma unroll
    for (int j = 0; j < 8; j++) {
        float w = P * g[j];
        float c = fmaf(-mu, w, kbe[j]);
        float z = fmaf(h[j], w, c);
        float q, rc;
        asm("ex2.approx.f32 %0, %1;" : "=f"(q) : "f"(z));
        float sum = q + 1.0f;
        asm("rcp.approx.f32 %0, %1;" : "=f"(rc) : "f"(sum));
        h[j] = fmaf(-2.0f, rc, 1.0f);
    }
}

__device__ __forceinline__ void gemm8(const float hin[8], float hout[8],
                                      const float* __restrict__ W,
                                      const float* __restrict__ b) {
#pragma unroll
    for (int j = 0; j < 8; j++) {
        float a = b[j];
#pragma unroll
        for (int k = 0; k < 8; k++) a = fmaf(hin[k], W[k * 8 + j], a);
        hout[j] = a;
    }
}

__device__ __forceinline__ void load_idx(
    const int* __restrict__ ei, size_t E, int e0, int is64,
    int& s0, int& s1, int& d0, int& d1)
{
    if (is64) {
        int4 sw = *(const int4*)(ei + 2 * (size_t)e0);
        int4 dw = *(const int4*)(ei + 2 * (E + (size_t)e0));
        s0 = sw.x; s1 = sw.z; d0 = dw.x; d1 = dw.z;
    } else {
        int2 sw = *(const int2*)(ei + e0);
        int2 dw = *(const int2*)(ei + E + (size_t)e0);
        s0 = sw.x; s1 = sw.y; d0 = dw.x; d1 = dw.y;
    }
}

__global__ void __launch_bounds__(128, 3) edge_k(
    const int* __restrict__ ei, int E,
    const float* __restrict__ g1, const float* __restrict__ be1,
    const float* __restrict__ W2, const float* __restrict__ b2,
    const float* __restrict__ g2, const float* __restrict__ be2,
    const float* __restrict__ W3, const float* __restrict__ b3,
    const float* __restrict__ g3, const float* __restrict__ be3,
    const float* __restrict__ W4, const float* __restrict__ b4,
    float* __restrict__ out)
{
    __shared__ float sW2[64], sW3[64], sW4[8];
    __shared__ float sv[64];  // g1,Kbe1,b2,g2,Kbe2,b3,g3,Kbe3
    __shared__ float sb4;
    __shared__ int sflag;
    int t = threadIdx.x;
    if (t == 0) { sflag = detect_is64(ei); sb4 = b4[0]; }
    if (t < 64) { sW2[t] = W2[t]; sW3[t] = W3[t]; }
    if (t < 8) {
        sW4[t] = W4[t];
        sv[t]      = g1[t];  sv[8 + t]  = KLOG2E * be1[t];
        sv[16 + t] = b2[t];  sv[24 + t] = g2[t];  sv[32 + t] = KLOG2E * be2[t];
        sv[40 + t] = b3[t];  sv[48 + t] = g3[t];  sv[56 + t] = KLOG2E * be3[t];
    }
    __syncthreads();

    const float* sg1 = sv;       const float* skb1 = sv + 8;
    const float* sb2 = sv + 16;  const float* sg2  = sv + 24; const float* skb2 = sv + 32;
    const float* sb3 = sv + 40;  const float* sg3  = sv + 48; const float* skb3 = sv + 56;

    const int is64 = sflag;
    const int stride2 = gridDim.x * blockDim.x * 2;
    int e0 = (blockIdx.x * blockDim.x + t) * 2;

    int s0 = 0, s1 = 0, d0 = 0, d1 = 0;
    bool pv = (e0 + 1 < E);
    if (pv) load_idx(ei, (size_t)E, e0, is64, s0, s1, d0, d1);

    while (e0 < E) {
        int e1 = e0 + stride2;
        if (pv) {
            // prefetch next iteration's indices
            int ns0 = 0, ns1 = 0, nd0 = 0, nd1 = 0;
            bool npv = (e1 + 1 < E);
            if (npv) load_idx(ei, (size_t)E, e1, is64, ns0, ns1, nd0, nd1);

            const float4* apA = (const float4*)(g_xs + (size_t)s0 * 8);
            const float4* bpA = (const float4*)(g_xb + (size_t)d0 * 8);
            const float4* apB = (const float4*)(g_xs + (size_t)s1 * 8);
            const float4* bpB = (const float4*)(g_xb + (size_t)d1 * 8);
            float4 a0A = apA[0], a1A = apA[1], c0A = bpA[0], c1A = bpA[1];
            float4 a0B = apB[0], a1B = apB[1], c0B = bpB[0], c1B = bpB[1];

            float hA[8] = { a0A.x + c0A.x, a0A.y + c0A.y, a0A.z + c0A.z, a0A.w + c0A.w,
                            a1A.x + c1A.x, a1A.y + c1A.y, a1A.z + c1A.z, a1A.w + c1A.w };
            float hB[8] = { a0B.x + c0B.x, a0B.y + c0B.y, a0B.z + c0B.z, a0B.w + c0B.w,
                            a1B.x + c1B.x, a1B.y + c1B.y, a1B.z + c1B.z, a1B.w + c1B.w };

            ln_tanh(hA, sg1, skb1);            ln_tanh(hB, sg1, skb1);
            float h2A[8], h2B[8];
            gemm8(hA, h2A, sW2, sb2);          gemm8(hB, h2B, sW2, sb2);
            ln_tanh(h2A, sg2, skb2);           ln_tanh(h2B, sg2, skb2);
            float h3A[8], h3B[8];
            gemm8(h2A, h3A, sW3, sb3);         gemm8(h2B, h3B, sW3, sb3);
            ln_tanh(h3A, sg3, skb3);           ln_tanh(h3B, sg3, skb3);

            float oA = sb4, oB = sb4;
#pragma unroll
            for (int k = 0; k < 8; k++) { oA = fmaf(h3A[k], sW4[k], oA);
                                          oB = fmaf(h3B[k], sW4[k], oB); }
            *(float2*)(out + e0) = make_float2(oA, oB);

            s0 = ns0; s1 = ns1; d0 = nd0; d1 = nd1;
            pv = npv;
        } else {
            // scalar tail (e0 == E-1, only when E is odd)
            int s, d;
            if (is64) { s = ei[2 * (size_t)e0]; d = ei[2 * ((size_t)E + e0)]; }
            else      { s = ei[e0];             d = ei[(size_t)E + e0]; }
            const float4* ap = (const float4*)(g_xs + (size_t)s * 8);
            const float4* bp = (const float4*)(g_xb + (size_t)d * 8);
            float4 a0 = ap[0], a1 = ap[1], c0 = bp[0], c1 = bp[1];
            float h[8] = { a0.x + c0.x, a0.y + c0.y, a0.z + c0.z, a0.w + c0.w,
                           a1.x + c1.x, a1.y + c1.y, a1.z + c1.z, a1.w + c1.w };
            ln_tanh(h, sg1, skb1);
            float h2[8]; gemm8(h, h2, sW2, sb2);
            ln_tanh(h2, sg2, skb2);
            float h3[8]; gemm8(h2, h3, sW3, sb3);
            ln_tanh(h3, sg3, skb3);
            float o = sb4;
#pragma unroll
            for (int k = 0; k < 8; k++) o = fmaf(h3[k], sW4[k], o);
            out[e0] = o;
            pv = (e1 + 1 < E);
            if (pv) load_idx(ei, (size_t)E, e1, is64, s0, s1, d0, d1);
        }
        e0 = e1;
    }
}

// ---------------------------------------------------------------------------
extern "C" void kernel_launch(void* const* d_in, const int* in_sizes, int n_in,
                              void* d_out, int out_size)
{
    const float* x     = (const float*)d_in[0];
    const int*   ei    = (const int*)d_in[1];
    const float* vp    = (const float*)d_in[2];
    const int*   batch = (const int*)d_in[3];
    const float* W1  = (const float*)d_in[4];
    const float* b1  = (const float*)d_in[5];
    const float* g1  = (const float*)d_in[6];
    const float* be1 = (const float*)d_in[7];
    const float* W2  = (const float*)d_in[8];
    const float* b2  = (const float*)d_in[9];
    const float* g2  = (const float*)d_in[10];
    const float* be2 = (const float*)d_in[11];
    const float* W3  = (const float*)d_in[12];
    const float* b3  = (const float*)d_in[13];
    const float* g3  = (const float*)d_in[14];
    const float* be3 = (const float*)d_in[15];
    const float* W4  = (const float*)d_in[16];
    const float* b4  = (const float*)d_in[17];

    int N = in_sizes[0] / 16;
    int E = in_sizes[1] / 2;
    int G = in_sizes[2] / 16;

    int pb = (N + 255) / 256;
    pre_k<<<pb, 256>>>(x, batch, vp, W1, b1, ei, N, G);

    // persistent 1-wave grid: 3 blocks/SM x 148 SMs
    int eb = 444;
    long long need = ((long long)E / 2 + 127) / 128;
    if (need < eb) eb = (int)(need > 0 ? need : 1);
    edge_k<<<eb, 128>>>(ei, E, g1, be1, W2, b2, g2, be2, W3, b3, g3, be3,
                        W4, b4, (float*)d_out);
}